// round 1
// baseline (speedup 1.0000x reference)
#include <cuda_runtime.h>
#include <cstdint>

// BERT_CRF: B=64, S=512, H=768, L=9
// Strategy:
//   Kernel A (grid 64*16, block 128): per (batch, chunk of 32 timesteps):
//     - compute the 32 emission rows (fused GEMM, hidden read once total)
//     - build the chunk's 9x9 log-semiring product matrix (parallel scan trick)
//     - compute the chunk's numerator partial sum
//   Kernel B (grid 64, block 32): per batch: apply 16 chunk matrices to alpha0,
//     assemble numerator, write (denom - num).
//   Kernel C: deterministic 64 -> 1 reduction into d_out.

#define BB 64
#define SS 512
#define HH 768
#define LL 9
#define NC 16      // chunks per batch
#define CL 32      // timesteps per chunk
#define NST2 81    // 9*9

#define LOG2E 1.4426950408889634f
#define LN2   0.6931471805599453f

__device__ float g_em0[BB * LL];              // emissions at t=0 per batch
__device__ float g_P[BB * NC * NST2];         // chunk product matrices (base-2 log domain)
__device__ float g_numpart[BB * NC];          // numerator partials per chunk
__device__ float g_partial[BB];               // per-batch (denom - num)

__device__ __forceinline__ float ex2f_(float x) {
    float y; asm("ex2.approx.ftz.f32 %0, %1;" : "=f"(y) : "f"(x)); return y;
}
__device__ __forceinline__ float lg2f_(float x) {
    float y; asm("lg2.approx.ftz.f32 %0, %1;" : "=f"(y) : "f"(x)); return y;
}

// ---------------------------------------------------------------------------
// Kernel A
// ---------------------------------------------------------------------------
__global__ __launch_bounds__(128) void crf_chunk_kernel(
    const float* __restrict__ hidden,   // [B,S,H]
    const int*   __restrict__ mask,     // [B,S]
    const int*   __restrict__ labels,   // [B,S]
    const float* __restrict__ Wm,       // [H,L]
    const float* __restrict__ bias,     // [L]
    const float* __restrict__ trans)    // [L,L]
{
    __shared__ float sW[HH * 12];       // W rows padded to 12 floats (16B-aligned rows)
    __shared__ float sEm[CL * LL];      // natural-log-domain emissions for this chunk
    __shared__ float sT[NST2];          // natural trans
    __shared__ float sP[2][NST2];       // double-buffered chunk matrix (base-2)
    __shared__ float sRed[128 * LL];    // GEMM partial reduction
    __shared__ int   sMask[CL];

    const int tid = threadIdx.x;
    const int b = blockIdx.x / NC;
    const int c = blockIdx.x % NC;

    // ---- phase 0: stage W (padded) and trans into shared ----
    for (int i = tid; i < HH * LL; i += 128) {
        int k = i / LL, l = i - k * LL;
        sW[k * 12 + l] = Wm[i];
    }
    if (tid < NST2) sT[tid] = trans[tid];
    __syncthreads();

    // ---- phase 1: emissions for rows t in [c*CL, c*CL+32) ----
    // warp w owns k-slice [w*192, w*192+192); lane r owns row r.
    {
        const int w = tid >> 5;
        const int r = tid & 31;
        const int row = c * CL + r;
        const float* hrow = hidden + ((size_t)b * SS + row) * HH + w * 192;
        const float4* h4 = (const float4*)hrow;

        float acc[LL];
#pragma unroll
        for (int l = 0; l < LL; ++l) acc[l] = 0.f;

#pragma unroll 2
        for (int kq = 0; kq < 48; ++kq) {
            float4 h = h4[kq];
            const float* wbase = &sW[(w * 192 + kq * 4) * 12];
#pragma unroll
            for (int s = 0; s < 4; ++s) {
                float hv = (s == 0) ? h.x : (s == 1) ? h.y : (s == 2) ? h.z : h.w;
                const float4 wa = *(const float4*)(wbase + s * 12);
                const float4 wb = *(const float4*)(wbase + s * 12 + 4);
                const float  wc = *(wbase + s * 12 + 8);
                acc[0] = fmaf(hv, wa.x, acc[0]);
                acc[1] = fmaf(hv, wa.y, acc[1]);
                acc[2] = fmaf(hv, wa.z, acc[2]);
                acc[3] = fmaf(hv, wa.w, acc[3]);
                acc[4] = fmaf(hv, wb.x, acc[4]);
                acc[5] = fmaf(hv, wb.y, acc[5]);
                acc[6] = fmaf(hv, wb.z, acc[6]);
                acc[7] = fmaf(hv, wb.w, acc[7]);
                acc[8] = fmaf(hv, wc,   acc[8]);
            }
        }
#pragma unroll
        for (int l = 0; l < LL; ++l) sRed[tid * LL + l] = acc[l];
    }
    __syncthreads();

    if (tid < CL) {
        const int r = tid;
        float em[LL];
#pragma unroll
        for (int l = 0; l < LL; ++l) {
            em[l] = bias[l]
                  + sRed[(r)      * LL + l]
                  + sRed[(32 + r) * LL + l]
                  + sRed[(64 + r) * LL + l]
                  + sRed[(96 + r) * LL + l];
            sEm[r * LL + l] = em[l];
        }
        sMask[r] = mask[b * SS + c * CL + r];
        if (c == 0 && r == 0) {
#pragma unroll
            for (int l = 0; l < LL; ++l) g_em0[b * LL + l] = em[l];
        }
    }
    // identity init of the chunk matrix (base-2 log domain)
    if (tid < 96) {
        int lane = tid & 31;
        int e = (tid >> 5) * 27 + lane;
        if (lane < 27) {
            int i = e / LL, j = e - i * LL;
            sP[0][e] = (i == j) ? 0.f : -1e30f;
        }
    }
    __syncthreads();

    if (tid >= 96) {
        // ---- warp 3: numerator partial for this chunk ----
        const int l = tid - 96;            // 0..31
        const int t = c * CL + l;
        float v = 0.f;
        if (t >= 1 && sMask[l]) {
            int lt  = labels[b * SS + t];
            int ltp = labels[b * SS + t - 1];
            v = sT[ltp * LL + lt] + sEm[l * LL + lt];
        }
#pragma unroll
        for (int o = 16; o > 0; o >>= 1) v += __shfl_xor_sync(0xffffffffu, v, o);
        if (l == 0) g_numpart[b * NC + c] = v;
    } else {
        // ---- warps 0-2: log-semiring chunk matrix scan ----
        const int lane = tid & 31;
        const int e = (tid >> 5) * 27 + lane;   // entry id, valid when lane<27 (e<81)
        const bool act = (lane < 27);
        const int i = e / LL;
        const int j = e - i * LL;

        float Tcol[LL];
        if (act) {
#pragma unroll
            for (int k = 0; k < LL; ++k) Tcol[k] = sT[k * LL + j] * LOG2E;
        }

        int cur = 0;
        const int t0 = (c == 0) ? 1 : c * CL;
        const int t1 = c * CL + CL;
        for (int t = t0; t < t1; ++t) {
            if (!sMask[t - c * CL]) continue;   // uniform across block
            float pn = 0.f;
            if (act) {
                const float* Pr = &sP[cur][i * LL];
                float x[LL];
                float mx = -1e30f;
#pragma unroll
                for (int k = 0; k < LL; ++k) {
                    x[k] = Pr[k] + Tcol[k];
                    mx = fmaxf(mx, x[k]);
                }
                float s = 0.f;
#pragma unroll
                for (int k = 0; k < LL; ++k) s += ex2f_(x[k] - mx);
                pn = fmaf(sEm[(t - c * CL) * LL + j], LOG2E, mx + lg2f_(s));
                sP[cur ^ 1][e] = pn;
            }
            asm volatile("bar.sync 1, 96;" ::: "memory");
            cur ^= 1;
        }
        if (act) g_P[((size_t)b * NC + c) * NST2 + e] = sP[cur][e];
    }
}

// ---------------------------------------------------------------------------
// Kernel B: per-batch finalize
// ---------------------------------------------------------------------------
__global__ __launch_bounds__(32) void crf_final_kernel(
    const int*   __restrict__ mask,
    const int*   __restrict__ labels,
    const float* __restrict__ start_t,
    const float* __restrict__ end_t)
{
    const int b = blockIdx.x;
    const int lane = threadIdx.x;
    __shared__ float sPm[NC * NST2];

    for (int idx = lane; idx < NC * NST2; idx += 32)
        sPm[idx] = g_P[(size_t)b * NC * NST2 + idx];

    int ms = 0;
    for (int t = lane; t < SS; t += 32) ms += mask[b * SS + t];
#pragma unroll
    for (int o = 16; o > 0; o >>= 1) ms += __shfl_xor_sync(0xffffffffu, ms, o);

    float np = (lane < NC) ? g_numpart[b * NC + lane] : 0.f;
#pragma unroll
    for (int o = 16; o > 0; o >>= 1) np += __shfl_xor_sync(0xffffffffu, np, o);

    __syncwarp();

    // alpha0 (base-2), replicated across lanes
    const int jj = (lane < LL) ? lane : 0;
    float a[LL];
#pragma unroll
    for (int q = 0; q < LL; ++q)
        a[q] = LOG2E * (start_t[q] + g_em0[b * LL + q]);

    for (int cc = 0; cc < NC; ++cc) {
        float x[LL];
        float mx = -1e30f;
#pragma unroll
        for (int q = 0; q < LL; ++q) {
            x[q] = a[q] + sPm[cc * NST2 + q * LL + jj];
            mx = fmaxf(mx, x[q]);
        }
        float s = 0.f;
#pragma unroll
        for (int q = 0; q < LL; ++q) s += ex2f_(x[q] - mx);
        float pn = mx + lg2f_(s);
#pragma unroll
        for (int q = 0; q < LL; ++q) a[q] = __shfl_sync(0xffffffffu, pn, q);
    }

    // denom = LN2 * log2sumexp(a + log2e*end)
    float x[LL];
    float mx = -1e30f;
#pragma unroll
    for (int q = 0; q < LL; ++q) {
        x[q] = fmaf(end_t[q], LOG2E, a[q]);
        mx = fmaxf(mx, x[q]);
    }
    float s = 0.f;
#pragma unroll
    for (int q = 0; q < LL; ++q) s += ex2f_(x[q] - mx);
    float denom = LN2 * (mx + lg2f_(s));

    if (lane == 0) {
        int last = ms - 1;
        int lab0 = labels[b * SS];
        int labL = labels[b * SS + last];
        float num = start_t[lab0] + g_em0[b * LL + lab0] + np + end_t[labL];
        g_partial[b] = denom - num;
    }
}

// ---------------------------------------------------------------------------
// Kernel C: deterministic 64 -> 1 reduction
// ---------------------------------------------------------------------------
__global__ __launch_bounds__(64) void crf_reduce_kernel(float* __restrict__ out)
{
    const int t = threadIdx.x;
    float v = g_partial[t];
#pragma unroll
    for (int o = 16; o > 0; o >>= 1) v += __shfl_xor_sync(0xffffffffu, v, o);
    __shared__ float sh[2];
    if ((t & 31) == 0) sh[t >> 5] = v;
    __syncthreads();
    if (t == 0) out[0] = sh[0] + sh[1];
}

// ---------------------------------------------------------------------------
extern "C" void kernel_launch(void* const* d_in, const int* in_sizes, int n_in,
                              void* d_out, int out_size)
{
    (void)in_sizes; (void)n_in; (void)out_size;
    const float* hidden  = (const float*)d_in[0];
    const int*   mask    = (const int*)  d_in[1];
    const int*   labels  = (const int*)  d_in[2];
    const float* Wm      = (const float*)d_in[3];
    const float* bias    = (const float*)d_in[4];
    const float* start_t = (const float*)d_in[5];
    const float* end_t   = (const float*)d_in[6];
    const float* trans   = (const float*)d_in[7];

    crf_chunk_kernel<<<BB * NC, 128>>>(hidden, mask, labels, Wm, bias, trans);
    crf_final_kernel<<<BB, 32>>>(mask, labels, start_t, end_t);
    crf_reduce_kernel<<<1, 64>>>((float*)d_out);
}

// round 4
// speedup vs baseline: 1.2181x; 1.2181x over previous
#include <cuda_runtime.h>
#include <cstdint>

// BERT_CRF: B=64, S=512, H=768, L=9
//   Kernel A (grid 64*16, block 128): per (batch, time-chunk of 32):
//     - fused emissions GEMM (H tile staged via smem, coalesced; W broadcast from smem)
//     - chunk 9x9 log-semiring product matrix (3-warp parallel scan, warp 3 = numerator)
//   Kernel B (grid 64, block 32): apply 16 chunk matrices, assemble per-batch loss.
//   Kernel C: deterministic 64 -> 1 reduction.

#define BB 64
#define SS 512
#define HH 768
#define LL 9
#define NC 16      // time chunks per batch
#define CL 32      // timesteps per chunk
#define NST2 81    // 9*9
#define KC 96      // k-chunk width
#define NKC 8      // 768 / 96

#define LOG2E 1.4426950408889634f
#define LN2   0.6931471805599453f

__device__ float g_em0[BB * LL];
__device__ float g_P[BB * NC * NST2];
__device__ float g_numpart[BB * NC];
__device__ float g_partial[BB];

__device__ __forceinline__ float ex2f_(float x) {
    float y; asm("ex2.approx.ftz.f32 %0, %1;" : "=f"(y) : "f"(x)); return y;
}
__device__ __forceinline__ float lg2f_(float x) {
    float y; asm("lg2.approx.ftz.f32 %0, %1;" : "=f"(y) : "f"(x)); return y;
}

// ---------------------------------------------------------------------------
// Kernel A
// ---------------------------------------------------------------------------
__global__ __launch_bounds__(128) void crf_chunk_kernel(
    const float* __restrict__ hidden,   // [B,S,H]
    const int*   __restrict__ mask,     // [B,S]
    const int*   __restrict__ labels,   // [B,S]
    const float* __restrict__ Wm,       // [H,L] contiguous, stride 9
    const float* __restrict__ bias,     // [L]
    const float* __restrict__ trans)    // [L,L]
{
    __shared__ float sW[HH * LL];        // 27648 B, unpadded stride-9 rows
    __shared__ float sH[CL * 100];       // 12800 B, padded row stride 100 floats
    __shared__ float sEm[CL * LL];       // emissions (natural log) for this chunk
    __shared__ float sT[NST2];
    __shared__ float sP[2][NST2];
    __shared__ int   sMask[CL];

    float* sRed = sH;                    // alias: reduction buffer reuses sH

    const int tid = threadIdx.x;
    const int b  = blockIdx.x / NC;
    const int tc = blockIdx.x % NC;

    // ---- stage W (full, float4) and trans ----
    {
        const float4* W4 = (const float4*)Wm;
        for (int i = tid; i < (HH * LL) / 4; i += 128)
            ((float4*)sW)[i] = W4[i];
    }
    if (tid < NST2) sT[tid] = trans[tid];

    // ---- fused GEMM over 8 k-chunks of 96 ----
    const int w = tid >> 5;              // warp id: owns k-locals [24w, 24w+24) of each chunk
    const int r = tid & 31;              // lane: row within time chunk
    const int srow = tid >> 2;           // staging row
    const int sc   = tid & 3;            // staging col group

    const float* gsrc = hidden + ((size_t)(b * SS + tc * CL + srow)) * HH + sc * 4;

    float acc[LL];
#pragma unroll
    for (int l = 0; l < LL; ++l) acc[l] = 0.f;

    float4 pf[6];
#pragma unroll
    for (int i = 0; i < 6; ++i)
        pf[i] = *(const float4*)(gsrc + i * 16);

    for (int kc = 0; kc < NKC; ++kc) {
        __syncthreads();   // prior compute done reading sH
#pragma unroll
        for (int i = 0; i < 6; ++i)
            *(float4*)&sH[srow * 100 + sc * 4 + i * 16] = pf[i];
        if (kc < NKC - 1) {
            const float* gn = gsrc + (kc + 1) * KC;
#pragma unroll
            for (int i = 0; i < 6; ++i)
                pf[i] = *(const float4*)(gn + i * 16);
        }
        __syncthreads();   // sH tile ready

#pragma unroll
        for (int g = 0; g < 6; ++g) {
            const int kl = w * 24 + g * 4;              // local k (mult of 4)
            float4 h = *(const float4*)&sH[r * 100 + kl];
            const int k0 = kc * KC + kl;                // global k (mult of 4)
            float wreg[36];
#pragma unroll
            for (int q = 0; q < 9; ++q)
                *(float4*)&wreg[q * 4] = *(const float4*)&sW[k0 * LL + q * 4];
#pragma unroll
            for (int s = 0; s < 4; ++s) {
                float hv = (s == 0) ? h.x : (s == 1) ? h.y : (s == 2) ? h.z : h.w;
#pragma unroll
                for (int l = 0; l < LL; ++l)
                    acc[l] = fmaf(hv, wreg[s * LL + l], acc[l]);
            }
        }
    }

    __syncthreads();       // all reads of sH done before aliasing as sRed
#pragma unroll
    for (int l = 0; l < LL; ++l) sRed[tid * LL + l] = acc[l];
    __syncthreads();

    if (tid < CL) {
        float em[LL];
#pragma unroll
        for (int l = 0; l < LL; ++l) {
            em[l] = bias[l]
                  + sRed[(tid)      * LL + l]
                  + sRed[(32 + tid) * LL + l]
                  + sRed[(64 + tid) * LL + l]
                  + sRed[(96 + tid) * LL + l];
            sEm[tid * LL + l] = em[l];
        }
        sMask[tid] = mask[b * SS + tc * CL + tid];
        if (tc == 0 && tid == 0) {
#pragma unroll
            for (int l = 0; l < LL; ++l) g_em0[b * LL + l] = em[l];
        }
    }
    if (tid < 96) {
        int lane = tid & 31;
        int e = (tid >> 5) * 27 + lane;
        if (lane < 27) {
            int i = e / LL, j = e - i * LL;
            sP[0][e] = (i == j) ? 0.f : -1e30f;
        }
    }
    __syncthreads();

    if (tid >= 96) {
        // ---- warp 3: numerator partial ----
        const int l = tid - 96;
        const int t = tc * CL + l;
        float v = 0.f;
        if (t >= 1 && sMask[l]) {
            int lt  = labels[b * SS + t];
            int ltp = labels[b * SS + t - 1];
            v = sT[ltp * LL + lt] + sEm[l * LL + lt];
        }
#pragma unroll
        for (int o = 16; o > 0; o >>= 1) v += __shfl_xor_sync(0xffffffffu, v, o);
        if (l == 0) g_numpart[b * NC + tc] = v;
    } else {
        // ---- warps 0-2: log-semiring chunk-matrix scan (base-2) ----
        const int lane = tid & 31;
        const int e = (tid >> 5) * 27 + lane;
        const bool act = (lane < 27);
        const int i = e / LL;
        const int j = e - i * LL;

        float Tcol[LL];
        if (act) {
#pragma unroll
            for (int k = 0; k < LL; ++k) Tcol[k] = sT[k * LL + j] * LOG2E;
        }

        int cur = 0;
        const int t0 = (tc == 0) ? 1 : tc * CL;
        const int t1 = tc * CL + CL;
        for (int t = t0; t < t1; ++t) {
            if (!sMask[t - tc * CL]) continue;   // block-uniform
            if (act) {
                const float* Pr = &sP[cur][i * LL];
                float x[LL];
                float mx = -1e30f;
#pragma unroll
                for (int k = 0; k < LL; ++k) {
                    x[k] = Pr[k] + Tcol[k];
                    mx = fmaxf(mx, x[k]);
                }
                float s = 0.f;
#pragma unroll
                for (int k = 0; k < LL; ++k) s += ex2f_(x[k] - mx);
                sP[cur ^ 1][e] = fmaf(sEm[(t - tc * CL) * LL + j], LOG2E,
                                      mx + lg2f_(s));
            }
            asm volatile("bar.sync 1, 96;" ::: "memory");
            cur ^= 1;
        }
        if (act) g_P[((size_t)b * NC + tc) * NST2 + e] = sP[cur][e];
    }
}

// ---------------------------------------------------------------------------
// Kernel B: per-batch finalize
// ---------------------------------------------------------------------------
__global__ __launch_bounds__(32) void crf_final_kernel(
    const int*   __restrict__ mask,
    const int*   __restrict__ labels,
    const float* __restrict__ start_t,
    const float* __restrict__ end_t)
{
    const int b = blockIdx.x;
    const int lane = threadIdx.x;
    __shared__ float sPm[NC * NST2];

    for (int idx = lane; idx < NC * NST2; idx += 32)
        sPm[idx] = g_P[(size_t)b * NC * NST2 + idx];

    int ms = 0;
    for (int t = lane; t < SS; t += 32) ms += mask[b * SS + t];
#pragma unroll
    for (int o = 16; o > 0; o >>= 1) ms += __shfl_xor_sync(0xffffffffu, ms, o);

    float np = (lane < NC) ? g_numpart[b * NC + lane] : 0.f;
#pragma unroll
    for (int o = 16; o > 0; o >>= 1) np += __shfl_xor_sync(0xffffffffu, np, o);

    __syncwarp();

    const int jj = (lane < LL) ? lane : 0;
    float a[LL];
#pragma unroll
    for (int q = 0; q < LL; ++q)
        a[q] = LOG2E * (start_t[q] + g_em0[b * LL + q]);

    for (int cc = 0; cc < NC; ++cc) {
        float x[LL];
        float mx = -1e30f;
#pragma unroll
        for (int q = 0; q < LL; ++q) {
            x[q] = a[q] + sPm[cc * NST2 + q * LL + jj];
            mx = fmaxf(mx, x[q]);
        }
        float s = 0.f;
#pragma unroll
        for (int q = 0; q < LL; ++q) s += ex2f_(x[q] - mx);
        float pn = mx + lg2f_(s);
#pragma unroll
        for (int q = 0; q < LL; ++q) a[q] = __shfl_sync(0xffffffffu, pn, q);
    }

    float x[LL];
    float mx = -1e30f;
#pragma unroll
    for (int q = 0; q < LL; ++q) {
        x[q] = fmaf(end_t[q], LOG2E, a[q]);
        mx = fmaxf(mx, x[q]);
    }
    float s = 0.f;
#pragma unroll
    for (int q = 0; q < LL; ++q) s += ex2f_(x[q] - mx);
    float denom = LN2 * (mx + lg2f_(s));

    if (lane == 0) {
        int last = ms - 1;
        int lab0 = labels[b * SS];
        int labL = labels[b * SS + last];
        float num = start_t[lab0] + g_em0[b * LL + lab0] + np + end_t[labL];
        g_partial[b] = denom - num;
    }
}

// ---------------------------------------------------------------------------
// Kernel C: deterministic 64 -> 1 reduction
// ---------------------------------------------------------------------------
__global__ __launch_bounds__(64) void crf_reduce_kernel(float* __restrict__ out)
{
    const int t = threadIdx.x;
    float v = g_partial[t];
#pragma unroll
    for (int o = 16; o > 0; o >>= 1) v += __shfl_xor_sync(0xffffffffu, v, o);
    __shared__ float sh[2];
    if ((t & 31) == 0) sh[t >> 5] = v;
    __syncthreads();
    if (t == 0) out[0] = sh[0] + sh[1];
}

// ---------------------------------------------------------------------------
extern "C" void kernel_launch(void* const* d_in, const int* in_sizes, int n_in,
                              void* d_out, int out_size)
{
    (void)in_sizes; (void)n_in; (void)out_size;
    const float* hidden  = (const float*)d_in[0];
    const int*   mask    = (const int*)  d_in[1];
    const int*   labels  = (const int*)  d_in[2];
    const float* Wm      = (const float*)d_in[3];
    const float* bias    = (const float*)d_in[4];
    const float* start_t = (const float*)d_in[5];
    const float* end_t   = (const float*)d_in[6];
    const float* trans   = (const float*)d_in[7];

    crf_chunk_kernel<<<BB * NC, 128>>>(hidden, mask, labels, Wm, bias, trans);
    crf_final_kernel<<<BB, 32>>>(mask, labels, start_t, end_t);
    crf_reduce_kernel<<<1, 64>>>((float*)d_out);
}

// round 5
// speedup vs baseline: 1.3543x; 1.1118x over previous
#include <cuda_runtime.h>
#include <cstdint>

// BERT_CRF: B=64, S=512, H=768, L=9
//   Kernel 1 (emis): grid 512, block 256 — 64 rows/block emissions GEMM,
//     cp.async double-buffered H tiles, W broadcast from smem -> g_Em.
//   Kernel 2 (scan): grid 64*16, block 128 — per (batch, 32-step chunk):
//     9x9 log-semiring product matrix + numerator partial, reading g_Em (L2).
//   Kernel 3 (final): grid 64, block 32 — apply 16 chunk matrices, per-batch loss.
//   Kernel 4: deterministic 64 -> 1 reduction.

#define BB 64
#define SS 512
#define HH 768
#define LL 9
#define NC 16       // time chunks per batch
#define CL 32       // timesteps per chunk
#define NST2 81
#define RPB 64      // rows per emis block
#define KC2 48      // k-chunk width
#define NKC2 16     // 768/48
#define SHS 52      // sH row stride (floats); 52 mod 32 = 20, gcd 4 -> conflict-free

#define LOG2E 1.4426950408889634f
#define LN2   0.6931471805599453f

__device__ __align__(16) float g_Em[BB * SS * LL];   // natural-log emissions
__device__ float g_P[BB * NC * NST2];
__device__ float g_numpart[BB * NC];
__device__ float g_partial[BB];

__device__ __forceinline__ float ex2f_(float x) {
    float y; asm("ex2.approx.ftz.f32 %0, %1;" : "=f"(y) : "f"(x)); return y;
}
__device__ __forceinline__ float lg2f_(float x) {
    float y; asm("lg2.approx.ftz.f32 %0, %1;" : "=f"(y) : "f"(x)); return y;
}
__device__ __forceinline__ void cp16(void* dst, const void* src) {
    uint32_t d = (uint32_t)__cvta_generic_to_shared(dst);
    asm volatile("cp.async.cg.shared.global [%0], [%1], 16;" :: "r"(d), "l"(src));
}
__device__ __forceinline__ void cp_commit() {
    asm volatile("cp.async.commit_group;");
}
template <int N> __device__ __forceinline__ void cp_wait() {
    asm volatile("cp.async.wait_group %0;" :: "n"(N));
}

// ---------------------------------------------------------------------------
// Kernel 1: emissions GEMM
// ---------------------------------------------------------------------------
__global__ __launch_bounds__(256) void emis_kernel(
    const float* __restrict__ hidden,   // [B*S, H]
    const float* __restrict__ Wm,       // [H, L]
    const float* __restrict__ bias)     // [L]
{
    __shared__ float sW[HH * LL];            // 27648 B
    __shared__ float sH[2][RPB * SHS];       // 2 x 13312 B

    const int tid = threadIdx.x;
    const size_t row0 = (size_t)blockIdx.x * RPB;

    // stage W (uniform-broadcast source for compute)
    {
        const float4* W4 = (const float4*)Wm;
        for (int i = tid; i < (HH * LL) / 4; i += 256)
            ((float4*)sW)[i] = W4[i];
    }

    const int srow = tid >> 2;               // 0..63
    const int sc   = tid & 3;
    const float* gsrc = hidden + (row0 + srow) * HH + sc * 4;

    // prologue: async-load chunk 0 into buf 0
#pragma unroll
    for (int i = 0; i < 3; ++i)
        cp16(&sH[0][srow * SHS + sc * 4 + i * 16], gsrc + i * 16);
    cp_commit();

    const int w = tid >> 5;
    const int r = tid & 31;
    const int rloc = (w >> 2) * 32 + r;      // local row
    const int ks   = (w & 3) * 12;           // local k-slice start

    float acc[LL];
#pragma unroll
    for (int l = 0; l < LL; ++l) acc[l] = 0.f;

    for (int kc = 0; kc < NKC2; ++kc) {
        if (kc + 1 < NKC2) {                  // issue next chunk into other buffer
            const float* gn = gsrc + (kc + 1) * KC2;
            float* dst = &sH[(kc + 1) & 1][srow * SHS + sc * 4];
#pragma unroll
            for (int i = 0; i < 3; ++i)
                cp16(dst + i * 16, gn + i * 16);
            cp_commit();
            cp_wait<1>();                     // chunk kc complete
        } else {
            cp_wait<0>();
        }
        __syncthreads();

        const float* hb = &sH[kc & 1][rloc * SHS];
#pragma unroll
        for (int g = 0; g < 3; ++g) {
            const int kl = ks + g * 4;
            float4 h = *(const float4*)&hb[kl];
            const int k0 = kc * KC2 + kl;     // multiple of 4
            float wreg[36];
#pragma unroll
            for (int q = 0; q < 9; ++q)
                *(float4*)&wreg[q * 4] = ((const float4*)&sW[k0 * LL])[q];
#pragma unroll
            for (int s = 0; s < 4; ++s) {
                float hv = (s == 0) ? h.x : (s == 1) ? h.y : (s == 2) ? h.z : h.w;
#pragma unroll
                for (int l = 0; l < LL; ++l)
                    acc[l] = fmaf(hv, wreg[s * LL + l], acc[l]);
            }
        }
        __syncthreads();                      // buffer consumed; safe for reuse
    }

    // reduction: 4 k-slice partials per row
    float* sRed = &sH[0][0];                  // 2304 floats
    float* sOut = &sH[0][2432];               // 576 floats, 16B-aligned offset
#pragma unroll
    for (int l = 0; l < LL; ++l) sRed[tid * LL + l] = acc[l];
    __syncthreads();

    if (tid < RPB) {
        const int hi = tid >> 5;              // row half
        const int lo = tid & 31;
#pragma unroll
        for (int l = 0; l < LL; ++l) {
            float em = bias[l];
#pragma unroll
            for (int s = 0; s < 4; ++s)
                em += sRed[((hi * 4 + s) * 32 + lo) * LL + l];
            sOut[tid * LL + l] = em;
        }
    }
    __syncthreads();

    float4* out4 = (float4*)(g_Em + row0 * LL);
    for (int i = tid; i < (RPB * LL) / 4; i += 256)   // 144 float4
        out4[i] = ((const float4*)sOut)[i];
}

// ---------------------------------------------------------------------------
// Kernel 2: chunk scan (3 warps matrix scan + 1 warp numerator)
// ---------------------------------------------------------------------------
__global__ __launch_bounds__(128) void scan_kernel(
    const int*   __restrict__ mask,     // [B,S]
    const int*   __restrict__ labels,   // [B,S]
    const float* __restrict__ trans)    // [L,L]
{
    __shared__ float sEm[CL * LL];      // natural-log emissions for this chunk
    __shared__ float sT[NST2];
    __shared__ float sP[2][NST2];
    __shared__ int   sMask[CL];

    const int tid = threadIdx.x;
    const int b  = blockIdx.x / NC;
    const int tc = blockIdx.x % NC;

    if (tid < 72)
        ((float4*)sEm)[tid] =
            ((const float4*)(g_Em + ((size_t)b * SS + tc * CL) * LL))[tid];
    if (tid < NST2) sT[tid] = trans[tid];
    if (tid < CL)  sMask[tid] = mask[b * SS + tc * CL + tid];
    if (tid < 96) {
        int lane = tid & 31;
        int e = (tid >> 5) * 27 + lane;
        if (lane < 27) {
            int i = e / LL, j = e - i * LL;
            sP[0][e] = (i == j) ? 0.f : -1e30f;
        }
    }
    __syncthreads();

    if (tid >= 96) {
        // warp 3: numerator partial
        const int l = tid - 96;
        const int t = tc * CL + l;
        float v = 0.f;
        if (t >= 1 && sMask[l]) {
            int lt  = labels[b * SS + t];
            int ltp = labels[b * SS + t - 1];
            v = sT[ltp * LL + lt] + sEm[l * LL + lt];
        }
#pragma unroll
        for (int o = 16; o > 0; o >>= 1) v += __shfl_xor_sync(0xffffffffu, v, o);
        if (l == 0) g_numpart[b * NC + tc] = v;
    } else {
        // warps 0-2: log-semiring chunk-matrix scan (base-2)
        const int lane = tid & 31;
        const int e = (tid >> 5) * 27 + lane;
        const bool act = (lane < 27);
        const int i = e / LL;
        const int j = e - i * LL;

        float Tcol[LL];
        if (act) {
#pragma unroll
            for (int k = 0; k < LL; ++k) Tcol[k] = sT[k * LL + j] * LOG2E;
        }

        int cur = 0;
        const int t0 = (tc == 0) ? 1 : tc * CL;
        const int t1 = tc * CL + CL;
        for (int t = t0; t < t1; ++t) {
            if (!sMask[t - tc * CL]) continue;   // block-uniform
            if (act) {
                const float* Pr = &sP[cur][i * LL];
                float x[LL];
                float mx = -1e30f;
#pragma unroll
                for (int k = 0; k < LL; ++k) {
                    x[k] = Pr[k] + Tcol[k];
                    mx = fmaxf(mx, x[k]);
                }
                float s = 0.f;
#pragma unroll
                for (int k = 0; k < LL; ++k) s += ex2f_(x[k] - mx);
                sP[cur ^ 1][e] = fmaf(sEm[(t - tc * CL) * LL + j], LOG2E,
                                      mx + lg2f_(s));
            }
            asm volatile("bar.sync 1, 96;" ::: "memory");
            cur ^= 1;
        }
        if (act) g_P[((size_t)b * NC + tc) * NST2 + e] = sP[cur][e];
    }
}

// ---------------------------------------------------------------------------
// Kernel 3: per-batch finalize
// ---------------------------------------------------------------------------
__global__ __launch_bounds__(32) void crf_final_kernel(
    const int*   __restrict__ mask,
    const int*   __restrict__ labels,
    const float* __restrict__ start_t,
    const float* __restrict__ end_t)
{
    const int b = blockIdx.x;
    const int lane = threadIdx.x;
    __shared__ float sPm[NC * NST2];

    for (int idx = lane; idx < NC * NST2; idx += 32)
        sPm[idx] = g_P[(size_t)b * NC * NST2 + idx];

    int ms = 0;
    for (int t = lane; t < SS; t += 32) ms += mask[b * SS + t];
#pragma unroll
    for (int o = 16; o > 0; o >>= 1) ms += __shfl_xor_sync(0xffffffffu, ms, o);

    float np = (lane < NC) ? g_numpart[b * NC + lane] : 0.f;
#pragma unroll
    for (int o = 16; o > 0; o >>= 1) np += __shfl_xor_sync(0xffffffffu, np, o);

    __syncwarp();

    const float* em0 = g_Em + (size_t)b * SS * LL;    // t = 0 row
    const int jj = (lane < LL) ? lane : 0;
    float a[LL];
#pragma unroll
    for (int q = 0; q < LL; ++q)
        a[q] = LOG2E * (start_t[q] + em0[q]);

    for (int cc = 0; cc < NC; ++cc) {
        float x[LL];
        float mx = -1e30f;
#pragma unroll
        for (int q = 0; q < LL; ++q) {
            x[q] = a[q] + sPm[cc * NST2 + q * LL + jj];
            mx = fmaxf(mx, x[q]);
        }
        float s = 0.f;
#pragma unroll
        for (int q = 0; q < LL; ++q) s += ex2f_(x[q] - mx);
        float pn = mx + lg2f_(s);
#pragma unroll
        for (int q = 0; q < LL; ++q) a[q] = __shfl_sync(0xffffffffu, pn, q);
    }

    float x[LL];
    float mx = -1e30f;
#pragma unroll
    for (int q = 0; q < LL; ++q) {
        x[q] = fmaf(end_t[q], LOG2E, a[q]);
        mx = fmaxf(mx, x[q]);
    }
    float s = 0.f;
#pragma unroll
    for (int q = 0; q < LL; ++q) s += ex2f_(x[q] - mx);
    float denom = LN2 * (mx + lg2f_(s));

    if (lane == 0) {
        int last = ms - 1;
        int lab0 = labels[b * SS];
        int labL = labels[b * SS + last];
        float num = start_t[lab0] + em0[lab0] + np + end_t[labL];
        g_partial[b] = denom - num;
    }
}

// ---------------------------------------------------------------------------
// Kernel 4: deterministic 64 -> 1 reduction
// ---------------------------------------------------------------------------
__global__ __launch_bounds__(64) void crf_reduce_kernel(float* __restrict__ out)
{
    const int t = threadIdx.x;
    float v = g_partial[t];
#pragma unroll
    for (int o = 16; o > 0; o >>= 1) v += __shfl_xor_sync(0xffffffffu, v, o);
    __shared__ float sh[2];
    if ((t & 31) == 0) sh[t >> 5] = v;
    __syncthreads();
    if (t == 0) out[0] = sh[0] + sh[1];
}

// ---------------------------------------------------------------------------
extern "C" void kernel_launch(void* const* d_in, const int* in_sizes, int n_in,
                              void* d_out, int out_size)
{
    (void)in_sizes; (void)n_in; (void)out_size;
    const float* hidden  = (const float*)d_in[0];
    const int*   mask    = (const int*)  d_in[1];
    const int*   labels  = (const int*)  d_in[2];
    const float* Wm      = (const float*)d_in[3];
    const float* bias    = (const float*)d_in[4];
    const float* start_t = (const float*)d_in[5];
    const float* end_t   = (const float*)d_in[6];
    const float* trans   = (const float*)d_in[7];

    emis_kernel<<<(BB * SS) / RPB, 256>>>(hidden, Wm, bias);
    scan_kernel<<<BB * NC, 128>>>(mask, labels, trans);
    crf_final_kernel<<<BB, 32>>>(mask, labels, start_t, end_t);
    crf_reduce_kernel<<<1, 64>>>((float*)d_out);
}